// round 15
// baseline (speedup 1.0000x reference)
#include <cuda_runtime.h>
#include <stdint.h>

#define N_NODES 50000
#define DIM     128        // D == O == 128
#define E_MAX   800016     // per-relation edge capacity (problem fixes E=800000)
#define A_PAD   132        // shared A row stride (bank-conflict-free scalar frags)

#define NROWS2  (2 * N_NODES)                      // interleaved rows: g = 2*row + rel
#define SCAN_B  256
#define NBLK    ((NROWS2 + SCAN_B - 1) / SCAN_B)   // 391

// ---------------------------------------------------------------------------
// Static scratch (no cudaMalloc allowed). g_cnt is ZERO at entry to every
// kernel_launch call: zero-initialized static on the first call, and
// scanBC_kernel (whose last reader, scanA, has already finished) re-zeros it
// on every call.
// ---------------------------------------------------------------------------
__device__ float g_x[2 * N_NODES * DIM];     // [rel][node][dim]  (51.2 MB)

__device__ int  g_cnt[NROWS2];               // per-(row,rel) edge counts
__device__ int  g_off[NROWS2 + 1];           // CSR row pointers (interleaved)
__device__ int  g_bsum[NBLK];                // scanA block sums
__device__ int  g_rank1[E_MAX];              // per-edge rank within row (rel 0)
__device__ int  g_rank2[E_MAX];              // per-edge rank within row (rel 1)
__device__ int2 g_edge[2 * E_MAX];           // packed (rel*N + col, val-bits)

__device__ __forceinline__ uint32_t f2tf32(float f) {
    uint32_t r;
    asm("cvt.rna.tf32.f32 %0, %1;" : "=r"(r) : "f"(f));
    return r;
}

// ---------------------------------------------------------------------------
// Histogram over BOTH relations, interleaved row id g = 2*row + rel.
// The atomicAdd return value IS each edge's rank within its (row,rel) -- it
// is stored so the scatter pass needs no atomics. Requires g_cnt == 0.
// ---------------------------------------------------------------------------
__global__ void __launch_bounds__(256)
hist4_kernel(const int* __restrict__ r1, const int* __restrict__ r2,
             int E1, int E2)
{
    const int V1 = (E1 + 3) >> 2;
    const int V2 = (E2 + 3) >> 2;
    int v = blockIdx.x * blockDim.x + threadIdx.x;
    const int* rows; int* rank; int E, rel;
    if (v < V1)            { rows = r1; rank = g_rank1; E = E1; rel = 0; }
    else if (v < V1 + V2)  { rows = r2; rank = g_rank2; E = E2; rel = 1; v -= V1; }
    else return;

    const int i = v * 4;
    if (i + 3 < E) {
        const int4 r = __ldg(reinterpret_cast<const int4*>(rows) + v);
        int4 k;
        k.x = atomicAdd(&g_cnt[2 * r.x + rel], 1);
        k.y = atomicAdd(&g_cnt[2 * r.y + rel], 1);
        k.z = atomicAdd(&g_cnt[2 * r.z + rel], 1);
        k.w = atomicAdd(&g_cnt[2 * r.w + rel], 1);
        reinterpret_cast<int4*>(rank)[v] = k;
    } else {
        for (int e = i; e < E; ++e)
            rank[e] = atomicAdd(&g_cnt[2 * __ldg(rows + e) + rel], 1);
    }
}

// ---------------------------------------------------------------------------
// Scan stage A: coalesced block-local exclusive scan of g_cnt -> g_off,
// block totals -> g_bsum.
// ---------------------------------------------------------------------------
__global__ void __launch_bounds__(SCAN_B)
scanA_kernel()
{
    __shared__ int sh[SCAN_B];
    const int t = threadIdx.x;
    const int i = blockIdx.x * SCAN_B + t;
    const int v = (i < NROWS2) ? g_cnt[i] : 0;
    sh[t] = v;
    __syncthreads();
    #pragma unroll
    for (int d = 1; d < SCAN_B; d <<= 1) {
        int u = (t >= d) ? sh[t - d] : 0;
        __syncthreads();
        sh[t] += u;
        __syncthreads();
    }
    if (i < NROWS2) g_off[i] = sh[t] - v;           // block-local exclusive
    if (t == SCAN_B - 1) g_bsum[blockIdx.x] = sh[t];
}

// ---------------------------------------------------------------------------
// Scan stage BC (merged): each block INDEPENDENTLY reduces bsum[j < bid]
// and applies the base. Also restores g_cnt == 0 (scanA, the last reader of
// g_cnt, finished before this launch).
// ---------------------------------------------------------------------------
__global__ void __launch_bounds__(SCAN_B)
scanBC_kernel()
{
    __shared__ int sh[SCAN_B];
    const int t   = threadIdx.x;
    const int bid = blockIdx.x;

    int s = 0;
    if (t         < bid && t         < NBLK) s += g_bsum[t];
    if (t + SCAN_B < bid && t + SCAN_B < NBLK) s += g_bsum[t + SCAN_B];
    sh[t] = s;
    __syncthreads();
    #pragma unroll
    for (int d = SCAN_B / 2; d > 0; d >>= 1) {
        if (t < d) sh[t] += sh[t + d];
        __syncthreads();
    }
    const int base = sh[0];

    const int i = bid * SCAN_B + t;
    if (i < NROWS2) {
        g_off[i] += base;
        g_cnt[i] = 0;                                  // invariant restore
    }
    if (bid == NBLK - 1 && t == 0)
        g_off[NROWS2] = base + g_bsum[NBLK - 1];       // grand total sentinel
}

// ---------------------------------------------------------------------------
// Scatter over BOTH relations -- ATOMIC-FREE: slot = g_off[2*row+rel] + rank.
// Stores the pre-combined gather index cidx = rel*N + col so the SpMM is
// relation-oblivious.
// ---------------------------------------------------------------------------
__global__ void __launch_bounds__(256)
scatter4_kernel(const int* __restrict__ r1, const int* __restrict__ c1,
                const float* __restrict__ v1,
                const int* __restrict__ r2, const int* __restrict__ c2,
                const float* __restrict__ v2,
                int E1, int E2)
{
    const int V1 = (E1 + 3) >> 2;
    const int V2 = (E2 + 3) >> 2;
    int v = blockIdx.x * blockDim.x + threadIdx.x;
    const int* rows; const int* cols; const float* vals; const int* rank;
    int E, rel;
    if (v < V1)           { rows = r1; cols = c1; vals = v1; rank = g_rank1; E = E1; rel = 0; }
    else if (v < V1 + V2) { rows = r2; cols = c2; vals = v2; rank = g_rank2; E = E2; rel = 1; v -= V1; }
    else return;

    const int cbase = rel * N_NODES;
    const int i = v * 4;
    if (i + 3 < E) {
        const int4   r = __ldg(reinterpret_cast<const int4*>(rows) + v);
        const int4   c = __ldg(reinterpret_cast<const int4*>(cols) + v);
        const float4 w = __ldg(reinterpret_cast<const float4*>(vals) + v);
        const int4   k = *(reinterpret_cast<const int4*>(rank) + v);
        const int p0 = __ldg(&g_off[2 * r.x + rel]) + k.x;
        const int p1 = __ldg(&g_off[2 * r.y + rel]) + k.y;
        const int p2 = __ldg(&g_off[2 * r.z + rel]) + k.z;
        const int p3 = __ldg(&g_off[2 * r.w + rel]) + k.w;
        g_edge[p0] = make_int2(cbase + c.x, __float_as_int(w.x));
        g_edge[p1] = make_int2(cbase + c.y, __float_as_int(w.y));
        g_edge[p2] = make_int2(cbase + c.z, __float_as_int(w.z));
        g_edge[p3] = make_int2(cbase + c.w, __float_as_int(w.w));
    } else {
        for (int e = i; e < E; ++e) {
            const int p = __ldg(&g_off[2 * __ldg(rows + e) + rel]) + rank[e];
            g_edge[p] = make_int2(cbase + __ldg(cols + e),
                                  __float_as_int(__ldg(vals + e)));
        }
    }
}

// ---------------------------------------------------------------------------
// Dense projection on tensor cores (proven 41.6 us form; output target is
// now the unified g_x with per-relation offset).
// ---------------------------------------------------------------------------
__global__ void __launch_bounds__(256)
gemm_tf32_kernel(const float* __restrict__ in,
                 const float* __restrict__ W1,
                 const float* __restrict__ W2)
{
    __shared__ uint32_t shA[64 * A_PAD];

    const int tid  = threadIdx.x;
    const int warp = tid >> 5;
    const int lane = tid & 31;
    const float* __restrict__ W    = blockIdx.y ? W2 : W1;
    float*       __restrict__ xout = g_x + (size_t)blockIdx.y * N_NODES * DIM;

    const int col0 = warp * 16;
    uint32_t Bf[2][16][2];
    #pragma unroll
    for (int nt = 0; nt < 2; ++nt) {
        const int n = col0 + nt * 8 + (lane >> 2);
        #pragma unroll
        for (int kk = 0; kk < 16; ++kk) {
            const int k = kk * 8 + (lane & 3);
            Bf[nt][kk][0] = f2tf32(__ldg(W + k * DIM + n));
            Bf[nt][kk][1] = f2tf32(__ldg(W + (k + 4) * DIM + n));
        }
    }

    #pragma unroll
    for (int t = 0; t < 2; ++t) {
        const int row0 = blockIdx.x * 128 + t * 64;

        #pragma unroll
        for (int i = 0; i < 8; ++i) {
            int idx = tid + i * 256;
            int r   = idx >> 5;
            int c4  = idx & 31;
            float4 v = make_float4(0.f, 0.f, 0.f, 0.f);
            if (row0 + r < N_NODES)
                v = __ldg(reinterpret_cast<const float4*>(in + (size_t)(row0 + r) * DIM) + c4);
            uint32_t* s = shA + r * A_PAD + c4 * 4;
            s[0] = f2tf32(v.x); s[1] = f2tf32(v.y);
            s[2] = f2tf32(v.z); s[3] = f2tf32(v.w);
        }
        __syncthreads();

        #pragma unroll
        for (int rt = 0; rt < 4; ++rt) {
            float acc[2][4] = {};
            const uint32_t* sA = shA + (rt * 16) * A_PAD;
            #pragma unroll
            for (int kk = 0; kk < 16; ++kk) {
                const int r = lane >> 2, c = kk * 8 + (lane & 3);
                uint32_t a0 = sA[r * A_PAD + c];
                uint32_t a1 = sA[(r + 8) * A_PAD + c];
                uint32_t a2 = sA[r * A_PAD + c + 4];
                uint32_t a3 = sA[(r + 8) * A_PAD + c + 4];
                #pragma unroll
                for (int nt = 0; nt < 2; ++nt) {
                    asm volatile(
                        "mma.sync.aligned.m16n8k8.row.col.f32.tf32.tf32.f32 "
                        "{%0,%1,%2,%3}, {%4,%5,%6,%7}, {%8,%9}, {%0,%1,%2,%3};"
                        : "+f"(acc[nt][0]), "+f"(acc[nt][1]),
                          "+f"(acc[nt][2]), "+f"(acc[nt][3])
                        : "r"(a0), "r"(a1), "r"(a2), "r"(a3),
                          "r"(Bf[nt][kk][0]), "r"(Bf[nt][kk][1]));
                }
            }
            const int rowa = row0 + rt * 16 + (lane >> 2);
            const int rowb = rowa + 8;
            #pragma unroll
            for (int nt = 0; nt < 2; ++nt) {
                const int c = col0 + nt * 8 + 2 * (lane & 3);
                if (rowa < N_NODES)
                    *reinterpret_cast<float2*>(xout + (size_t)rowa * DIM + c) =
                        make_float2(acc[nt][0], acc[nt][1]);
                if (rowb < N_NODES)
                    *reinterpret_cast<float2*>(xout + (size_t)rowb * DIM + c) =
                        make_float2(acc[nt][2], acc[nt][3]);
            }
        }
        __syncthreads();   // shA reused by next tile
    }
}

// ---------------------------------------------------------------------------
// Segmented SpMM, warp-cooperative, ONE contiguous segment per row
// ([off[2r], off[2r+2]) spans both relations; cidx already encodes the
// relation's g_x offset). Single staging pipeline per row -- no mid-row
// serialization point. Fused ReLU, single non-atomic store.
// ---------------------------------------------------------------------------
__global__ void __launch_bounds__(256)
spmm_csr_kernel(float* __restrict__ out)
{
    __shared__ int shc[8][32];
    __shared__ int shv[8][32];

    const int warp = threadIdx.x >> 5;
    const int lane = threadIdx.x & 31;
    const int row  = blockIdx.x * 8 + warp;
    if (row >= N_NODES) return;

    const int s = g_off[2 * row];
    const int e = g_off[2 * row + 2];          // covers rel 0 AND rel 1

    float4 acc = make_float4(0.f, 0.f, 0.f, 0.f);
    int* shcw = shc[warp];
    int* shvw = shv[warp];

    for (int i = s; i < e; i += 32) {
        const int idx = i + lane;
        if (idx < e) {
            const int2 t = __ldg(&g_edge[idx]);
            shcw[lane] = t.x;
            shvw[lane] = t.y;
        }
        __syncwarp();
        const int m = min(e - i, 32);
        int j = 0;
        for (; j + 4 <= m; j += 4) {
            const int c0 = shcw[j],     c1 = shcw[j + 1];
            const int c2 = shcw[j + 2], c3 = shcw[j + 3];
            const float4 x0 = __ldg(reinterpret_cast<const float4*>(g_x + (size_t)c0 * DIM) + lane);
            const float4 x1 = __ldg(reinterpret_cast<const float4*>(g_x + (size_t)c1 * DIM) + lane);
            const float4 x2 = __ldg(reinterpret_cast<const float4*>(g_x + (size_t)c2 * DIM) + lane);
            const float4 x3 = __ldg(reinterpret_cast<const float4*>(g_x + (size_t)c3 * DIM) + lane);
            const float v0 = __int_as_float(shvw[j]);
            const float v1 = __int_as_float(shvw[j + 1]);
            const float v2 = __int_as_float(shvw[j + 2]);
            const float v3 = __int_as_float(shvw[j + 3]);
            acc.x = fmaf(v0, x0.x, acc.x); acc.y = fmaf(v0, x0.y, acc.y);
            acc.z = fmaf(v0, x0.z, acc.z); acc.w = fmaf(v0, x0.w, acc.w);
            acc.x = fmaf(v1, x1.x, acc.x); acc.y = fmaf(v1, x1.y, acc.y);
            acc.z = fmaf(v1, x1.z, acc.z); acc.w = fmaf(v1, x1.w, acc.w);
            acc.x = fmaf(v2, x2.x, acc.x); acc.y = fmaf(v2, x2.y, acc.y);
            acc.z = fmaf(v2, x2.z, acc.z); acc.w = fmaf(v2, x2.w, acc.w);
            acc.x = fmaf(v3, x3.x, acc.x); acc.y = fmaf(v3, x3.y, acc.y);
            acc.z = fmaf(v3, x3.z, acc.z); acc.w = fmaf(v3, x3.w, acc.w);
        }
        for (; j < m; ++j) {
            const int   c  = shcw[j];
            const float v  = __int_as_float(shvw[j]);
            const float4 xv = __ldg(reinterpret_cast<const float4*>(g_x + (size_t)c * DIM) + lane);
            acc.x = fmaf(v, xv.x, acc.x); acc.y = fmaf(v, xv.y, acc.y);
            acc.z = fmaf(v, xv.z, acc.z); acc.w = fmaf(v, xv.w, acc.w);
        }
        __syncwarp();
    }

    acc.x = fmaxf(acc.x, 0.f); acc.y = fmaxf(acc.y, 0.f);
    acc.z = fmaxf(acc.z, 0.f); acc.w = fmaxf(acc.w, 0.f);
    reinterpret_cast<float4*>(out + (size_t)row * DIM)[lane] = acc;
}

// ---------------------------------------------------------------------------
// Entry point. Fork-join stream capture: GEMM on a side stream in parallel
// with the CSR build chain; SpMM joins both branches. Stream/events created
// once (host-side, idempotent, no device memory).
//
// Inputs (metadata order):
//   0 inputs[N,128] f32 | 1 adj1_rows i32 | 2 adj1_cols i32 | 3 adj1_vals f32
//   4 adj2_rows i32 | 5 adj2_cols i32 | 6 adj2_vals f32
//   7 weights_1[128,128] f32 | 8 weights_2[128,128] f32
// Output: [N,128] f32.
// ---------------------------------------------------------------------------
static cudaStream_t s_side   = nullptr;
static cudaEvent_t  s_evFork = nullptr;
static cudaEvent_t  s_evJoin = nullptr;

extern "C" void kernel_launch(void* const* d_in, const int* in_sizes, int n_in,
                              void* d_out, int out_size)
{
    if (s_side == nullptr) {                   // one-time host resource init
        cudaStreamCreateWithFlags(&s_side, cudaStreamNonBlocking);
        cudaEventCreateWithFlags(&s_evFork, cudaEventDisableTiming);
        cudaEventCreateWithFlags(&s_evJoin, cudaEventDisableTiming);
    }

    const float* in  = (const float*)d_in[0];
    const int*   a1r = (const int*)  d_in[1];
    const int*   a1c = (const int*)  d_in[2];
    const float* a1v = (const float*)d_in[3];
    const int*   a2r = (const int*)  d_in[4];
    const int*   a2c = (const int*)  d_in[5];
    const float* a2v = (const float*)d_in[6];
    const float* W1  = (const float*)d_in[7];
    const float* W2  = (const float*)d_in[8];
    float*       out = (float*)d_out;

    const int E1 = in_sizes[1];
    const int E2 = in_sizes[4];

    const int Vtot = (E1 + 3) / 4 + (E2 + 3) / 4;
    const int eblk = (Vtot + 255) / 256;

    // ---- fork: GEMM branch on side stream ---------------------------------
    cudaEventRecord(s_evFork, 0);              // origin = capture (legacy) stream
    cudaStreamWaitEvent(s_side, s_evFork, 0);

    dim3 ggrid((N_NODES + 127) / 128, 2);
    gemm_tf32_kernel<<<ggrid, 256, 0, s_side>>>(in, W1, W2);
    cudaEventRecord(s_evJoin, s_side);

    // ---- main branch: CSR build (interleaved rows, atomic-free scatter) ---
    hist4_kernel<<<eblk, 256>>>(a1r, a2r, E1, E2);
    scanA_kernel<<<NBLK, SCAN_B>>>();
    scanBC_kernel<<<NBLK, SCAN_B>>>();         // also restores g_cnt == 0
    scatter4_kernel<<<eblk, 256>>>(a1r, a1c, a1v, a2r, a2c, a2v, E1, E2);

    // ---- join: SpMM needs both g_edge (build) and g_x (GEMM) --------------
    cudaStreamWaitEvent(0, s_evJoin, 0);
    spmm_csr_kernel<<<(N_NODES + 7) / 8, 256>>>(out);
}

// round 16
// speedup vs baseline: 1.0997x; 1.0997x over previous
#include <cuda_runtime.h>
#include <cuda_fp16.h>
#include <stdint.h>

#define N_NODES 50000
#define DIM     128        // D == O == 128
#define E_MAX   800016     // per-relation edge capacity (problem fixes E=800000)
#define A_PAD   132        // shared A row stride (bank-conflict-free scalar frags)

#define NROWS2  (2 * N_NODES)                      // interleaved rows: g = 2*row + rel
#define SCAN_B  256
#define NBLK    ((NROWS2 + SCAN_B - 1) / SCAN_B)   // 391

// ---------------------------------------------------------------------------
// Static scratch (no cudaMalloc allowed). g_cnt is ZERO at entry to every
// kernel_launch call: zero-initialized static on the first call, and
// scanBC_kernel (whose last reader, scanA, has already finished) re-zeros it
// on every call.
//
// g_xh holds the projected features in fp16 (25.6 MB): halves the SpMM's
// L1tex-wavefront count (2 per gather instead of 4) and its LTS gather
// traffic (410 MB instead of 819 MB). Precision: fp16 u = 2^-11; the
// segment-sum's relative error stays ~u (error and signal both scale sqrt(n)),
// RSS with tf32's 2.9e-4 -> ~4e-4, safely under the 1e-3 gate.
// ---------------------------------------------------------------------------
__device__ __half g_xh[2 * N_NODES * DIM];   // [rel][node][dim]  (25.6 MB)

__device__ int  g_cnt[NROWS2];               // per-(row,rel) edge counts
__device__ int  g_off[NROWS2 + 1];           // CSR row pointers (interleaved)
__device__ int  g_bsum[NBLK];                // scanA block sums
__device__ int  g_rank1[E_MAX];              // per-edge rank within row (rel 0)
__device__ int  g_rank2[E_MAX];              // per-edge rank within row (rel 1)
__device__ int2 g_edge[2 * E_MAX];           // packed (rel*N + col, val-bits)

__device__ __forceinline__ uint32_t f2tf32(float f) {
    uint32_t r;
    asm("cvt.rna.tf32.f32 %0, %1;" : "=r"(r) : "f"(f));
    return r;
}

// ---------------------------------------------------------------------------
// Histogram over BOTH relations, interleaved row id g = 2*row + rel.
// The atomicAdd return value IS each edge's rank within its (row,rel) -- it
// is stored so the scatter pass needs no atomics. Requires g_cnt == 0.
// ---------------------------------------------------------------------------
__global__ void __launch_bounds__(256)
hist4_kernel(const int* __restrict__ r1, const int* __restrict__ r2,
             int E1, int E2)
{
    const int V1 = (E1 + 3) >> 2;
    const int V2 = (E2 + 3) >> 2;
    int v = blockIdx.x * blockDim.x + threadIdx.x;
    const int* rows; int* rank; int E, rel;
    if (v < V1)            { rows = r1; rank = g_rank1; E = E1; rel = 0; }
    else if (v < V1 + V2)  { rows = r2; rank = g_rank2; E = E2; rel = 1; v -= V1; }
    else return;

    const int i = v * 4;
    if (i + 3 < E) {
        const int4 r = __ldg(reinterpret_cast<const int4*>(rows) + v);
        int4 k;
        k.x = atomicAdd(&g_cnt[2 * r.x + rel], 1);
        k.y = atomicAdd(&g_cnt[2 * r.y + rel], 1);
        k.z = atomicAdd(&g_cnt[2 * r.z + rel], 1);
        k.w = atomicAdd(&g_cnt[2 * r.w + rel], 1);
        reinterpret_cast<int4*>(rank)[v] = k;
    } else {
        for (int e = i; e < E; ++e)
            rank[e] = atomicAdd(&g_cnt[2 * __ldg(rows + e) + rel], 1);
    }
}

// ---------------------------------------------------------------------------
// Scan stage A: coalesced block-local exclusive scan of g_cnt -> g_off,
// block totals -> g_bsum.
// ---------------------------------------------------------------------------
__global__ void __launch_bounds__(SCAN_B)
scanA_kernel()
{
    __shared__ int sh[SCAN_B];
    const int t = threadIdx.x;
    const int i = blockIdx.x * SCAN_B + t;
    const int v = (i < NROWS2) ? g_cnt[i] : 0;
    sh[t] = v;
    __syncthreads();
    #pragma unroll
    for (int d = 1; d < SCAN_B; d <<= 1) {
        int u = (t >= d) ? sh[t - d] : 0;
        __syncthreads();
        sh[t] += u;
        __syncthreads();
    }
    if (i < NROWS2) g_off[i] = sh[t] - v;           // block-local exclusive
    if (t == SCAN_B - 1) g_bsum[blockIdx.x] = sh[t];
}

// ---------------------------------------------------------------------------
// Scan stage BC (merged): each block INDEPENDENTLY reduces bsum[j < bid]
// and applies the base. Also restores g_cnt == 0 (scanA, the last reader of
// g_cnt, finished before this launch).
// ---------------------------------------------------------------------------
__global__ void __launch_bounds__(SCAN_B)
scanBC_kernel()
{
    __shared__ int sh[SCAN_B];
    const int t   = threadIdx.x;
    const int bid = blockIdx.x;

    int s = 0;
    if (t         < bid && t         < NBLK) s += g_bsum[t];
    if (t + SCAN_B < bid && t + SCAN_B < NBLK) s += g_bsum[t + SCAN_B];
    sh[t] = s;
    __syncthreads();
    #pragma unroll
    for (int d = SCAN_B / 2; d > 0; d >>= 1) {
        if (t < d) sh[t] += sh[t + d];
        __syncthreads();
    }
    const int base = sh[0];

    const int i = bid * SCAN_B + t;
    if (i < NROWS2) {
        g_off[i] += base;
        g_cnt[i] = 0;                                  // invariant restore
    }
    if (bid == NBLK - 1 && t == 0)
        g_off[NROWS2] = base + g_bsum[NBLK - 1];       // grand total sentinel
}

// ---------------------------------------------------------------------------
// Scatter over BOTH relations -- ATOMIC-FREE: slot = g_off[2*row+rel] + rank.
// Stores the pre-combined gather index cidx = rel*N + col so the SpMM is
// relation-oblivious.
// ---------------------------------------------------------------------------
__global__ void __launch_bounds__(256)
scatter4_kernel(const int* __restrict__ r1, const int* __restrict__ c1,
                const float* __restrict__ v1,
                const int* __restrict__ r2, const int* __restrict__ c2,
                const float* __restrict__ v2,
                int E1, int E2)
{
    const int V1 = (E1 + 3) >> 2;
    const int V2 = (E2 + 3) >> 2;
    int v = blockIdx.x * blockDim.x + threadIdx.x;
    const int* rows; const int* cols; const float* vals; const int* rank;
    int E, rel;
    if (v < V1)           { rows = r1; cols = c1; vals = v1; rank = g_rank1; E = E1; rel = 0; }
    else if (v < V1 + V2) { rows = r2; cols = c2; vals = v2; rank = g_rank2; E = E2; rel = 1; v -= V1; }
    else return;

    const int cbase = rel * N_NODES;
    const int i = v * 4;
    if (i + 3 < E) {
        const int4   r = __ldg(reinterpret_cast<const int4*>(rows) + v);
        const int4   c = __ldg(reinterpret_cast<const int4*>(cols) + v);
        const float4 w = __ldg(reinterpret_cast<const float4*>(vals) + v);
        const int4   k = *(reinterpret_cast<const int4*>(rank) + v);
        const int p0 = __ldg(&g_off[2 * r.x + rel]) + k.x;
        const int p1 = __ldg(&g_off[2 * r.y + rel]) + k.y;
        const int p2 = __ldg(&g_off[2 * r.z + rel]) + k.z;
        const int p3 = __ldg(&g_off[2 * r.w + rel]) + k.w;
        g_edge[p0] = make_int2(cbase + c.x, __float_as_int(w.x));
        g_edge[p1] = make_int2(cbase + c.y, __float_as_int(w.y));
        g_edge[p2] = make_int2(cbase + c.z, __float_as_int(w.z));
        g_edge[p3] = make_int2(cbase + c.w, __float_as_int(w.w));
    } else {
        for (int e = i; e < E; ++e) {
            const int p = __ldg(&g_off[2 * __ldg(rows + e) + rel]) + rank[e];
            g_edge[p] = make_int2(cbase + __ldg(cols + e),
                                  __float_as_int(__ldg(vals + e)));
        }
    }
}

// ---------------------------------------------------------------------------
// Dense projection on tensor cores (proven 41.6 us mainloop, unchanged).
// Epilogue now emits fp16: adjacent column pairs (acc[nt][0], acc[nt][1])
// pack into one half2 store -- also halves the epilogue write traffic.
// ---------------------------------------------------------------------------
__global__ void __launch_bounds__(256)
gemm_tf32_kernel(const float* __restrict__ in,
                 const float* __restrict__ W1,
                 const float* __restrict__ W2)
{
    __shared__ uint32_t shA[64 * A_PAD];

    const int tid  = threadIdx.x;
    const int warp = tid >> 5;
    const int lane = tid & 31;
    const float* __restrict__ W = blockIdx.y ? W2 : W1;
    __half2* __restrict__ xout =
        reinterpret_cast<__half2*>(g_xh + (size_t)blockIdx.y * N_NODES * DIM);

    const int col0 = warp * 16;
    uint32_t Bf[2][16][2];
    #pragma unroll
    for (int nt = 0; nt < 2; ++nt) {
        const int n = col0 + nt * 8 + (lane >> 2);
        #pragma unroll
        for (int kk = 0; kk < 16; ++kk) {
            const int k = kk * 8 + (lane & 3);
            Bf[nt][kk][0] = f2tf32(__ldg(W + k * DIM + n));
            Bf[nt][kk][1] = f2tf32(__ldg(W + (k + 4) * DIM + n));
        }
    }

    #pragma unroll
    for (int t = 0; t < 2; ++t) {
        const int row0 = blockIdx.x * 128 + t * 64;

        #pragma unroll
        for (int i = 0; i < 8; ++i) {
            int idx = tid + i * 256;
            int r   = idx >> 5;
            int c4  = idx & 31;
            float4 v = make_float4(0.f, 0.f, 0.f, 0.f);
            if (row0 + r < N_NODES)
                v = __ldg(reinterpret_cast<const float4*>(in + (size_t)(row0 + r) * DIM) + c4);
            uint32_t* s = shA + r * A_PAD + c4 * 4;
            s[0] = f2tf32(v.x); s[1] = f2tf32(v.y);
            s[2] = f2tf32(v.z); s[3] = f2tf32(v.w);
        }
        __syncthreads();

        #pragma unroll
        for (int rt = 0; rt < 4; ++rt) {
            float acc[2][4] = {};
            const uint32_t* sA = shA + (rt * 16) * A_PAD;
            #pragma unroll
            for (int kk = 0; kk < 16; ++kk) {
                const int r = lane >> 2, c = kk * 8 + (lane & 3);
                uint32_t a0 = sA[r * A_PAD + c];
                uint32_t a1 = sA[(r + 8) * A_PAD + c];
                uint32_t a2 = sA[r * A_PAD + c + 4];
                uint32_t a3 = sA[(r + 8) * A_PAD + c + 4];
                #pragma unroll
                for (int nt = 0; nt < 2; ++nt) {
                    asm volatile(
                        "mma.sync.aligned.m16n8k8.row.col.f32.tf32.tf32.f32 "
                        "{%0,%1,%2,%3}, {%4,%5,%6,%7}, {%8,%9}, {%0,%1,%2,%3};"
                        : "+f"(acc[nt][0]), "+f"(acc[nt][1]),
                          "+f"(acc[nt][2]), "+f"(acc[nt][3])
                        : "r"(a0), "r"(a1), "r"(a2), "r"(a3),
                          "r"(Bf[nt][kk][0]), "r"(Bf[nt][kk][1]));
                }
            }
            const int rowa = row0 + rt * 16 + (lane >> 2);
            const int rowb = rowa + 8;
            #pragma unroll
            for (int nt = 0; nt < 2; ++nt) {
                const int c = col0 + nt * 8 + 2 * (lane & 3);
                if (rowa < N_NODES)
                    xout[(size_t)rowa * (DIM / 2) + (c >> 1)] =
                        __floats2half2_rn(acc[nt][0], acc[nt][1]);
                if (rowb < N_NODES)
                    xout[(size_t)rowb * (DIM / 2) + (c >> 1)] =
                        __floats2half2_rn(acc[nt][2], acc[nt][3]);
            }
        }
        __syncthreads();   // shA reused by next tile
    }
}

// ---------------------------------------------------------------------------
// Segmented SpMM, warp-cooperative, ONE contiguous segment per row. Gathers
// are fp16: 256 B/warp = 2 L1tex wavefronts (half of fp32's 4) -- this is
// the binding resource. Accumulation stays fp32. Fused ReLU, single store.
// ---------------------------------------------------------------------------
__global__ void __launch_bounds__(256)
spmm_csr_kernel(float* __restrict__ out)
{
    __shared__ int shc[8][32];
    __shared__ int shv[8][32];

    const int warp = threadIdx.x >> 5;
    const int lane = threadIdx.x & 31;
    const int row  = blockIdx.x * 8 + warp;
    if (row >= N_NODES) return;

    const int s = g_off[2 * row];
    const int e = g_off[2 * row + 2];          // covers rel 0 AND rel 1

    float4 acc = make_float4(0.f, 0.f, 0.f, 0.f);
    int* shcw = shc[warp];
    int* shvw = shv[warp];

    for (int i = s; i < e; i += 32) {
        const int idx = i + lane;
        if (idx < e) {
            const int2 t = __ldg(&g_edge[idx]);
            shcw[lane] = t.x;
            shvw[lane] = t.y;
        }
        __syncwarp();
        const int m = min(e - i, 32);
        int j = 0;
        for (; j + 4 <= m; j += 4) {
            const int c0 = shcw[j],     c1 = shcw[j + 1];
            const int c2 = shcw[j + 2], c3 = shcw[j + 3];
            // 4 independent fp16 gathers (uint2 = 4 halves per lane).
            const uint2 h0 = __ldg(reinterpret_cast<const uint2*>(g_xh + (size_t)c0 * DIM) + lane);
            const uint2 h1 = __ldg(reinterpret_cast<const uint2*>(g_xh + (size_t)c1 * DIM) + lane);
            const uint2 h2 = __ldg(reinterpret_cast<const uint2*>(g_xh + (size_t)c2 * DIM) + lane);
            const uint2 h3 = __ldg(reinterpret_cast<const uint2*>(g_xh + (size_t)c3 * DIM) + lane);
            const float v0 = __int_as_float(shvw[j]);
            const float v1 = __int_as_float(shvw[j + 1]);
            const float v2 = __int_as_float(shvw[j + 2]);
            const float v3 = __int_as_float(shvw[j + 3]);
            {
                const float2 a = __half22float2(*reinterpret_cast<const __half2*>(&h0.x));
                const float2 b = __half22float2(*reinterpret_cast<const __half2*>(&h0.y));
                acc.x = fmaf(v0, a.x, acc.x); acc.y = fmaf(v0, a.y, acc.y);
                acc.z = fmaf(v0, b.x, acc.z); acc.w = fmaf(v0, b.y, acc.w);
            }
            {
                const float2 a = __half22float2(*reinterpret_cast<const __half2*>(&h1.x));
                const float2 b = __half22float2(*reinterpret_cast<const __half2*>(&h1.y));
                acc.x = fmaf(v1, a.x, acc.x); acc.y = fmaf(v1, a.y, acc.y);
                acc.z = fmaf(v1, b.x, acc.z); acc.w = fmaf(v1, b.y, acc.w);
            }
            {
                const float2 a = __half22float2(*reinterpret_cast<const __half2*>(&h2.x));
                const float2 b = __half22float2(*reinterpret_cast<const __half2*>(&h2.y));
                acc.x = fmaf(v2, a.x, acc.x); acc.y = fmaf(v2, a.y, acc.y);
                acc.z = fmaf(v2, b.x, acc.z); acc.w = fmaf(v2, b.y, acc.w);
            }
            {
                const float2 a = __half22float2(*reinterpret_cast<const __half2*>(&h3.x));
                const float2 b = __half22float2(*reinterpret_cast<const __half2*>(&h3.y));
                acc.x = fmaf(v3, a.x, acc.x); acc.y = fmaf(v3, a.y, acc.y);
                acc.z = fmaf(v3, b.x, acc.z); acc.w = fmaf(v3, b.y, acc.w);
            }
        }
        for (; j < m; ++j) {
            const int   c  = shcw[j];
            const float v  = __int_as_float(shvw[j]);
            const uint2 h = __ldg(reinterpret_cast<const uint2*>(g_xh + (size_t)c * DIM) + lane);
            const float2 a = __half22float2(*reinterpret_cast<const __half2*>(&h.x));
            const float2 b = __half22float2(*reinterpret_cast<const __half2*>(&h.y));
            acc.x = fmaf(v, a.x, acc.x); acc.y = fmaf(v, a.y, acc.y);
            acc.z = fmaf(v, b.x, acc.z); acc.w = fmaf(v, b.y, acc.w);
        }
        __syncwarp();
    }

    acc.x = fmaxf(acc.x, 0.f); acc.y = fmaxf(acc.y, 0.f);
    acc.z = fmaxf(acc.z, 0.f); acc.w = fmaxf(acc.w, 0.f);
    // lane l owns columns [4l, 4l+4): uint2 gather covers halves 4l..4l+3.
    reinterpret_cast<float4*>(out + (size_t)row * DIM)[lane] = acc;
}

// ---------------------------------------------------------------------------
// Entry point. Fork-join stream capture: GEMM on a side stream in parallel
// with the CSR build chain; SpMM joins both branches. Stream/events created
// once (host-side, idempotent, no device memory).
//
// Inputs (metadata order):
//   0 inputs[N,128] f32 | 1 adj1_rows i32 | 2 adj1_cols i32 | 3 adj1_vals f32
//   4 adj2_rows i32 | 5 adj2_cols i32 | 6 adj2_vals f32
//   7 weights_1[128,128] f32 | 8 weights_2[128,128] f32
// Output: [N,128] f32.
// ---------------------------------------------------------------------------
static cudaStream_t s_side   = nullptr;
static cudaEvent_t  s_evFork = nullptr;
static cudaEvent_t  s_evJoin = nullptr;

extern "C" void kernel_launch(void* const* d_in, const int* in_sizes, int n_in,
                              void* d_out, int out_size)
{
    if (s_side == nullptr) {                   // one-time host resource init
        cudaStreamCreateWithFlags(&s_side, cudaStreamNonBlocking);
        cudaEventCreateWithFlags(&s_evFork, cudaEventDisableTiming);
        cudaEventCreateWithFlags(&s_evJoin, cudaEventDisableTiming);
    }

    const float* in  = (const float*)d_in[0];
    const int*   a1r = (const int*)  d_in[1];
    const int*   a1c = (const int*)  d_in[2];
    const float* a1v = (const float*)d_in[3];
    const int*   a2r = (const int*)  d_in[4];
    const int*   a2c = (const int*)  d_in[5];
    const float* a2v = (const float*)d_in[6];
    const float* W1  = (const float*)d_in[7];
    const float* W2  = (const float*)d_in[8];
    float*       out = (float*)d_out;

    const int E1 = in_sizes[1];
    const int E2 = in_sizes[4];

    const int Vtot = (E1 + 3) / 4 + (E2 + 3) / 4;
    const int eblk = (Vtot + 255) / 256;

    // ---- fork: GEMM branch on side stream ---------------------------------
    cudaEventRecord(s_evFork, 0);              // origin = capture (legacy) stream
    cudaStreamWaitEvent(s_side, s_evFork, 0);

    dim3 ggrid((N_NODES + 127) / 128, 2);
    gemm_tf32_kernel<<<ggrid, 256, 0, s_side>>>(in, W1, W2);
    cudaEventRecord(s_evJoin, s_side);

    // ---- main branch: CSR build (interleaved rows, atomic-free scatter) ---
    hist4_kernel<<<eblk, 256>>>(a1r, a2r, E1, E2);
    scanA_kernel<<<NBLK, SCAN_B>>>();
    scanBC_kernel<<<NBLK, SCAN_B>>>();         // also restores g_cnt == 0
    scatter4_kernel<<<eblk, 256>>>(a1r, a1c, a1v, a2r, a2c, a2v, E1, E2);

    // ---- join: SpMM needs both g_edge (build) and g_xh (GEMM) -------------
    cudaStreamWaitEvent(0, s_evJoin, 0);
    spmm_csr_kernel<<<(N_NODES + 7) / 8, 256>>>(out);
}

// round 17
// speedup vs baseline: 1.2062x; 1.0968x over previous
#include <cuda_runtime.h>
#include <cuda_fp16.h>
#include <stdint.h>

#define N_NODES 50000
#define DIM     128        // D == O == 128
#define E_MAX   800016     // per-relation edge capacity (problem fixes E=800000)
#define A_PADH  68         // shared A row stride in half2 words (64 data + 4 pad;
                           // 68 mod 32 == 4 -> conflict-free frags, same as 132)

#define NROWS2  (2 * N_NODES)                      // interleaved rows: g = 2*row + rel
#define SCAN_B  256
#define NBLK    ((NROWS2 + SCAN_B - 1) / SCAN_B)   // 391

// ---------------------------------------------------------------------------
// Static scratch (no cudaMalloc allowed). g_cnt is ZERO at entry to every
// kernel_launch call: zero-initialized static on the first call, and
// scanBC_kernel (whose last reader, scanA, has already finished) re-zeros it
// on every call.
// ---------------------------------------------------------------------------
__device__ __half g_xh[2 * N_NODES * DIM];   // [rel][node][dim]  (25.6 MB)

__device__ int  g_cnt[NROWS2];               // per-(row,rel) edge counts
__device__ int  g_off[NROWS2 + 1];           // CSR row pointers (interleaved)
__device__ int  g_bsum[NBLK];                // scanA block sums
__device__ int  g_rank1[E_MAX];              // per-edge rank within row (rel 0)
__device__ int  g_rank2[E_MAX];              // per-edge rank within row (rel 1)
__device__ int2 g_edge[2 * E_MAX];           // packed (rel*N + col, val-bits)

__device__ __forceinline__ uint32_t h2bits(__half2 h) {
    return *reinterpret_cast<uint32_t*>(&h);
}

// ---------------------------------------------------------------------------
// Histogram over BOTH relations, interleaved row id g = 2*row + rel.
// The atomicAdd return value IS each edge's rank within its (row,rel).
// Requires g_cnt == 0.
// ---------------------------------------------------------------------------
__global__ void __launch_bounds__(256)
hist4_kernel(const int* __restrict__ r1, const int* __restrict__ r2,
             int E1, int E2)
{
    const int V1 = (E1 + 3) >> 2;
    const int V2 = (E2 + 3) >> 2;
    int v = blockIdx.x * blockDim.x + threadIdx.x;
    const int* rows; int* rank; int E, rel;
    if (v < V1)            { rows = r1; rank = g_rank1; E = E1; rel = 0; }
    else if (v < V1 + V2)  { rows = r2; rank = g_rank2; E = E2; rel = 1; v -= V1; }
    else return;

    const int i = v * 4;
    if (i + 3 < E) {
        const int4 r = __ldg(reinterpret_cast<const int4*>(rows) + v);
        int4 k;
        k.x = atomicAdd(&g_cnt[2 * r.x + rel], 1);
        k.y = atomicAdd(&g_cnt[2 * r.y + rel], 1);
        k.z = atomicAdd(&g_cnt[2 * r.z + rel], 1);
        k.w = atomicAdd(&g_cnt[2 * r.w + rel], 1);
        reinterpret_cast<int4*>(rank)[v] = k;
    } else {
        for (int e = i; e < E; ++e)
            rank[e] = atomicAdd(&g_cnt[2 * __ldg(rows + e) + rel], 1);
    }
}

// ---------------------------------------------------------------------------
// Scan stage A: coalesced block-local exclusive scan of g_cnt -> g_off,
// block totals -> g_bsum.
// ---------------------------------------------------------------------------
__global__ void __launch_bounds__(SCAN_B)
scanA_kernel()
{
    __shared__ int sh[SCAN_B];
    const int t = threadIdx.x;
    const int i = blockIdx.x * SCAN_B + t;
    const int v = (i < NROWS2) ? g_cnt[i] : 0;
    sh[t] = v;
    __syncthreads();
    #pragma unroll
    for (int d = 1; d < SCAN_B; d <<= 1) {
        int u = (t >= d) ? sh[t - d] : 0;
        __syncthreads();
        sh[t] += u;
        __syncthreads();
    }
    if (i < NROWS2) g_off[i] = sh[t] - v;           // block-local exclusive
    if (t == SCAN_B - 1) g_bsum[blockIdx.x] = sh[t];
}

// ---------------------------------------------------------------------------
// Scan stage BC (merged): each block INDEPENDENTLY reduces bsum[j < bid]
// and applies the base. Also restores g_cnt == 0.
// ---------------------------------------------------------------------------
__global__ void __launch_bounds__(SCAN_B)
scanBC_kernel()
{
    __shared__ int sh[SCAN_B];
    const int t   = threadIdx.x;
    const int bid = blockIdx.x;

    int s = 0;
    if (t         < bid && t         < NBLK) s += g_bsum[t];
    if (t + SCAN_B < bid && t + SCAN_B < NBLK) s += g_bsum[t + SCAN_B];
    sh[t] = s;
    __syncthreads();
    #pragma unroll
    for (int d = SCAN_B / 2; d > 0; d >>= 1) {
        if (t < d) sh[t] += sh[t + d];
        __syncthreads();
    }
    const int base = sh[0];

    const int i = bid * SCAN_B + t;
    if (i < NROWS2) {
        g_off[i] += base;
        g_cnt[i] = 0;                                  // invariant restore
    }
    if (bid == NBLK - 1 && t == 0)
        g_off[NROWS2] = base + g_bsum[NBLK - 1];       // grand total sentinel
}

// ---------------------------------------------------------------------------
// Scatter over BOTH relations -- ATOMIC-FREE: slot = g_off[2*row+rel] + rank.
// Stores the pre-combined gather index cidx = rel*N + col.
// ---------------------------------------------------------------------------
__global__ void __launch_bounds__(256)
scatter4_kernel(const int* __restrict__ r1, const int* __restrict__ c1,
                const float* __restrict__ v1,
                const int* __restrict__ r2, const int* __restrict__ c2,
                const float* __restrict__ v2,
                int E1, int E2)
{
    const int V1 = (E1 + 3) >> 2;
    const int V2 = (E2 + 3) >> 2;
    int v = blockIdx.x * blockDim.x + threadIdx.x;
    const int* rows; const int* cols; const float* vals; const int* rank;
    int E, rel;
    if (v < V1)           { rows = r1; cols = c1; vals = v1; rank = g_rank1; E = E1; rel = 0; }
    else if (v < V1 + V2) { rows = r2; cols = c2; vals = v2; rank = g_rank2; E = E2; rel = 1; v -= V1; }
    else return;

    const int cbase = rel * N_NODES;
    const int i = v * 4;
    if (i + 3 < E) {
        const int4   r = __ldg(reinterpret_cast<const int4*>(rows) + v);
        const int4   c = __ldg(reinterpret_cast<const int4*>(cols) + v);
        const float4 w = __ldg(reinterpret_cast<const float4*>(vals) + v);
        const int4   k = *(reinterpret_cast<const int4*>(rank) + v);
        const int p0 = __ldg(&g_off[2 * r.x + rel]) + k.x;
        const int p1 = __ldg(&g_off[2 * r.y + rel]) + k.y;
        const int p2 = __ldg(&g_off[2 * r.z + rel]) + k.z;
        const int p3 = __ldg(&g_off[2 * r.w + rel]) + k.w;
        g_edge[p0] = make_int2(cbase + c.x, __float_as_int(w.x));
        g_edge[p1] = make_int2(cbase + c.y, __float_as_int(w.y));
        g_edge[p2] = make_int2(cbase + c.z, __float_as_int(w.z));
        g_edge[p3] = make_int2(cbase + c.w, __float_as_int(w.w));
    } else {
        for (int e = i; e < E; ++e) {
            const int p = __ldg(&g_off[2 * __ldg(rows + e) + rel]) + rank[e];
            g_edge[p] = make_int2(cbase + __ldg(cols + e),
                                  __float_as_int(__ldg(vals + e)));
        }
    }
}

// ---------------------------------------------------------------------------
// Dense projection on FP16 tensor cores (m16n8k16, fp32 accumulate).
// fp16 mantissa (11 bit) == tf32 mantissa, inputs are N(0,1): precision is
// unchanged vs the tf32 version, but MMA count halves, LDS count halves, and
// B fragments take 32 regs instead of 64. Same proven loop structure,
// fragment addressing, and padding property (A_PADH mod 32 == 4).
//
// m16n8k16 fragments (per PTX): A (16x16 f16, row-major) 4 regs:
//   a0=(r, 2c..2c+1) a1=(r+8, ..) a2=(r, 2c+8..) a3=(r+8, 2c+8..)
//   where r = lane>>2, c = lane&3. half2 word index in a 64-word row:
//   kk*8 + c (a0/a1), +4 (a2/a3).
// B (16x8 f16, col-major) 2 regs: b0=(k=2c..2c+1, n=lane>>2), b1=(k+8, n).
// D (16x8 f32) 4 regs: same layout as m16n8k8 -> epilogue unchanged.
// ---------------------------------------------------------------------------
__global__ void __launch_bounds__(256)
gemm_fp16_kernel(const float* __restrict__ in,
                 const float* __restrict__ W1,
                 const float* __restrict__ W2)
{
    __shared__ uint32_t shA[64 * A_PADH];      // half2 words, 17.4 KB

    const int tid  = threadIdx.x;
    const int warp = tid >> 5;
    const int lane = tid & 31;
    const float* __restrict__ W = blockIdx.y ? W2 : W1;
    __half2* __restrict__ xout =
        reinterpret_cast<__half2*>(g_xh + (size_t)blockIdx.y * N_NODES * DIM);

    // B fragments: warp w owns output cols [16w,16w+16), 8 k-steps of 16.
    const int col0 = warp * 16;
    uint32_t Bf[2][8][2];
    #pragma unroll
    for (int nt = 0; nt < 2; ++nt) {
        const int n = col0 + nt * 8 + (lane >> 2);
        #pragma unroll
        for (int kk = 0; kk < 8; ++kk) {
            const int k0 = kk * 16 + 2 * (lane & 3);
            Bf[nt][kk][0] = h2bits(__floats2half2_rn(
                __ldg(W + k0 * DIM + n), __ldg(W + (k0 + 1) * DIM + n)));
            Bf[nt][kk][1] = h2bits(__floats2half2_rn(
                __ldg(W + (k0 + 8) * DIM + n), __ldg(W + (k0 + 9) * DIM + n)));
        }
    }

    #pragma unroll
    for (int t = 0; t < 2; ++t) {
        const int row0 = blockIdx.x * 128 + t * 64;

        // Stage A tile (64 x 128) -> shared as half2 words.
        #pragma unroll
        for (int i = 0; i < 8; ++i) {
            int idx = tid + i * 256;
            int r   = idx >> 5;
            int c4  = idx & 31;                // float4 group: cols 4c4..4c4+3
            float4 v = make_float4(0.f, 0.f, 0.f, 0.f);
            if (row0 + r < N_NODES)
                v = __ldg(reinterpret_cast<const float4*>(in + (size_t)(row0 + r) * DIM) + c4);
            shA[r * A_PADH + 2 * c4]     = h2bits(__floats2half2_rn(v.x, v.y));
            shA[r * A_PADH + 2 * c4 + 1] = h2bits(__floats2half2_rn(v.z, v.w));
        }
        __syncthreads();

        #pragma unroll
        for (int rt = 0; rt < 4; ++rt) {
            float acc[2][4] = {};
            const uint32_t* sA = shA + (rt * 16) * A_PADH;
            const int r = lane >> 2;
            #pragma unroll
            for (int kk = 0; kk < 8; ++kk) {
                const int w = kk * 8 + (lane & 3);
                uint32_t a0 = sA[r * A_PADH + w];
                uint32_t a1 = sA[(r + 8) * A_PADH + w];
                uint32_t a2 = sA[r * A_PADH + w + 4];
                uint32_t a3 = sA[(r + 8) * A_PADH + w + 4];
                #pragma unroll
                for (int nt = 0; nt < 2; ++nt) {
                    asm volatile(
                        "mma.sync.aligned.m16n8k16.row.col.f32.f16.f16.f32 "
                        "{%0,%1,%2,%3}, {%4,%5,%6,%7}, {%8,%9}, {%0,%1,%2,%3};"
                        : "+f"(acc[nt][0]), "+f"(acc[nt][1]),
                          "+f"(acc[nt][2]), "+f"(acc[nt][3])
                        : "r"(a0), "r"(a1), "r"(a2), "r"(a3),
                          "r"(Bf[nt][kk][0]), "r"(Bf[nt][kk][1]));
                }
            }
            const int rowa = row0 + rt * 16 + (lane >> 2);
            const int rowb = rowa + 8;
            #pragma unroll
            for (int nt = 0; nt < 2; ++nt) {
                const int c = col0 + nt * 8 + 2 * (lane & 3);
                if (rowa < N_NODES)
                    xout[(size_t)rowa * (DIM / 2) + (c >> 1)] =
                        __floats2half2_rn(acc[nt][0], acc[nt][1]);
                if (rowb < N_NODES)
                    xout[(size_t)rowb * (DIM / 2) + (c >> 1)] =
                        __floats2half2_rn(acc[nt][2], acc[nt][3]);
            }
        }
        __syncthreads();   // shA reused by next tile
    }
}

// ---------------------------------------------------------------------------
// Segmented SpMM, warp-cooperative, ONE contiguous segment per row. fp16
// gathers (2 L1tex wavefronts each), fp32 accumulate, fused ReLU.
// (Unchanged from R15: near the LTS gather floor.)
// ---------------------------------------------------------------------------
__global__ void __launch_bounds__(256)
spmm_csr_kernel(float* __restrict__ out)
{
    __shared__ int shc[8][32];
    __shared__ int shv[8][32];

    const int warp = threadIdx.x >> 5;
    const int lane = threadIdx.x & 31;
    const int row  = blockIdx.x * 8 + warp;
    if (row >= N_NODES) return;

    const int s = g_off[2 * row];
    const int e = g_off[2 * row + 2];          // covers rel 0 AND rel 1

    float4 acc = make_float4(0.f, 0.f, 0.f, 0.f);
    int* shcw = shc[warp];
    int* shvw = shv[warp];

    for (int i = s; i < e; i += 32) {
        const int idx = i + lane;
        if (idx < e) {
            const int2 t = __ldg(&g_edge[idx]);
            shcw[lane] = t.x;
            shvw[lane] = t.y;
        }
        __syncwarp();
        const int m = min(e - i, 32);
        int j = 0;
        for (; j + 4 <= m; j += 4) {
            const int c0 = shcw[j],     c1 = shcw[j + 1];
            const int c2 = shcw[j + 2], c3 = shcw[j + 3];
            const uint2 h0 = __ldg(reinterpret_cast<const uint2*>(g_xh + (size_t)c0 * DIM) + lane);
            const uint2 h1 = __ldg(reinterpret_cast<const uint2*>(g_xh + (size_t)c1 * DIM) + lane);
            const uint2 h2 = __ldg(reinterpret_cast<const uint2*>(g_xh + (size_t)c2 * DIM) + lane);
            const uint2 h3 = __ldg(reinterpret_cast<const uint2*>(g_xh + (size_t)c3 * DIM) + lane);
            const float v0 = __int_as_float(shvw[j]);
            const float v1 = __int_as_float(shvw[j + 1]);
            const float v2 = __int_as_float(shvw[j + 2]);
            const float v3 = __int_as_float(shvw[j + 3]);
            {
                const float2 a = __half22float2(*reinterpret_cast<const __half2*>(&h0.x));
                const float2 b = __half22float2(*reinterpret_cast<const __half2*>(&h0.y));
                acc.x = fmaf(v0, a.x, acc.x); acc.y = fmaf(v0, a.y, acc.y);
                acc.z = fmaf(v0, b.x, acc.z); acc.w = fmaf(v0, b.y, acc.w);
            }
            {
                const float2 a = __half22float2(*reinterpret_cast<const __half2*>(&h1.x));
                const float2 b = __half22float2(*reinterpret_cast<const __half2*>(&h1.y));
                acc.x = fmaf(v1, a.x, acc.x); acc.y = fmaf(v1, a.y, acc.y);
                acc.z = fmaf(v1, b.x, acc.z); acc.w = fmaf(v1, b.y, acc.w);
            }
            {
                const float2 a = __half22float2(*reinterpret_cast<const __half2*>(&h2.x));
                const float2 b = __half22float2(*reinterpret_cast<const __half2*>(&h2.y));
                acc.x = fmaf(v2, a.x, acc.x); acc.y = fmaf(v2, a.y, acc.y);
                acc.z = fmaf(v2, b.x, acc.z); acc.w = fmaf(v2, b.y, acc.w);
            }
            {
                const float2 a = __half22float2(*reinterpret_cast<const __half2*>(&h3.x));
                const float2 b = __half22float2(*reinterpret_cast<const __half2*>(&h3.y));
                acc.x = fmaf(v3, a.x, acc.x); acc.y = fmaf(v3, a.y, acc.y);
                acc.z = fmaf(v3, b.x, acc.z); acc.w = fmaf(v3, b.y, acc.w);
            }
        }
        for (; j < m; ++j) {
            const int   c  = shcw[j];
            const float v  = __int_as_float(shvw[j]);
            const uint2 h = __ldg(reinterpret_cast<const uint2*>(g_xh + (size_t)c * DIM) + lane);
            const float2 a = __half22float2(*reinterpret_cast<const __half2*>(&h.x));
            const float2 b = __half22float2(*reinterpret_cast<const __half2*>(&h.y));
            acc.x = fmaf(v, a.x, acc.x); acc.y = fmaf(v, a.y, acc.y);
            acc.z = fmaf(v, b.x, acc.z); acc.w = fmaf(v, b.y, acc.w);
        }
        __syncwarp();
    }

    acc.x = fmaxf(acc.x, 0.f); acc.y = fmaxf(acc.y, 0.f);
    acc.z = fmaxf(acc.z, 0.f); acc.w = fmaxf(acc.w, 0.f);
    reinterpret_cast<float4*>(out + (size_t)row * DIM)[lane] = acc;
}

// ---------------------------------------------------------------------------
// Entry point. Fork-join stream capture: GEMM on a side stream in parallel
// with the CSR build chain; SpMM joins both branches. Stream/events created
// once (host-side, idempotent, no device memory).
//
// Inputs (metadata order):
//   0 inputs[N,128] f32 | 1 adj1_rows i32 | 2 adj1_cols i32 | 3 adj1_vals f32
//   4 adj2_rows i32 | 5 adj2_cols i32 | 6 adj2_vals f32
//   7 weights_1[128,128] f32 | 8 weights_2[128,128] f32
// Output: [N,128] f32.
// ---------------------------------------------------------------------------
static cudaStream_t s_side   = nullptr;
static cudaEvent_t  s_evFork = nullptr;
static cudaEvent_t  s_evJoin = nullptr;

extern "C" void kernel_launch(void* const* d_in, const int* in_sizes, int n_in,
                              void* d_out, int out_size)
{
    if (s_side == nullptr) {                   // one-time host resource init
        cudaStreamCreateWithFlags(&s_side, cudaStreamNonBlocking);
        cudaEventCreateWithFlags(&s_evFork, cudaEventDisableTiming);
        cudaEventCreateWithFlags(&s_evJoin, cudaEventDisableTiming);
    }

    const float* in  = (const float*)d_in[0];
    const int*   a1r = (const int*)  d_in[1];
    const int*   a1c = (const int*)  d_in[2];
    const float* a1v = (const float*)d_in[3];
    const int*   a2r = (const int*)  d_in[4];
    const int*   a2c = (const int*)  d_in[5];
    const float* a2v = (const float*)d_in[6];
    const float* W1  = (const float*)d_in[7];
    const float* W2  = (const float*)d_in[8];
    float*       out = (float*)d_out;

    const int E1 = in_sizes[1];
    const int E2 = in_sizes[4];

    const int Vtot = (E1 + 3) / 4 + (E2 + 3) / 4;
    const int eblk = (Vtot + 255) / 256;

    // ---- fork: GEMM branch on side stream ---------------------------------
    cudaEventRecord(s_evFork, 0);              // origin = capture (legacy) stream
    cudaStreamWaitEvent(s_side, s_evFork, 0);

    dim3 ggrid((N_NODES + 127) / 128, 2);
    gemm_fp16_kernel<<<ggrid, 256, 0, s_side>>>(in, W1, W2);
    cudaEventRecord(s_evJoin, s_side);

    // ---- main branch: CSR build (interleaved rows, atomic-free scatter) ---
    hist4_kernel<<<eblk, 256>>>(a1r, a2r, E1, E2);
    scanA_kernel<<<NBLK, SCAN_B>>>();
    scanBC_kernel<<<NBLK, SCAN_B>>>();         // also restores g_cnt == 0
    scatter4_kernel<<<eblk, 256>>>(a1r, a1c, a1v, a2r, a2c, a2v, E1, E2);

    // ---- join: SpMM needs both g_edge (build) and g_xh (GEMM) -------------
    cudaStreamWaitEvent(0, s_evJoin, 0);
    spmm_csr_kernel<<<(N_NODES + 7) / 8, 256>>>(out);
}